// round 15
// baseline (speedup 1.0000x reference)
#include <cuda_runtime.h>
#include <cuda_fp16.h>
#include <cstdint>

// x[8192,256] fp32 -> loss = mean_i 1/sqrt(max(2 - 2*max_{j!=i} s_ij, 1e-30))
// s = Xn Xn^T via mma.sync m16n8k16 fp16 (f32 accum), fused row/col max.
// GEMM config = round-7 best. Finalize folded into GEMM via last-CTA ticket:
// only 2 kernel launches total.

#define N 8192
#define D 256
#define BM 128
#define BN 128
#define BK 64                     // K elems per stage (fp16: 128 B per row)
#define NTH 256
#define NSTAGE (D / BK)           // 4
#define STAGE_BYTES 32768         // A 16KB + B 16KB
#define SMEM_DYN (2 * STAGE_BYTES)
#define NBK (N / BN)              // 64
#define NTILES (NBK * (NBK + 1) / 2)   // 2080

__device__ __half   g_xn[N * D];
__device__ unsigned g_rmax[N];
__device__ unsigned g_done;

__device__ __forceinline__ unsigned encf(float f) {
    unsigned u = __float_as_uint(f);
    return (u & 0x80000000u) ? ~u : (u | 0x80000000u);
}
__device__ __forceinline__ float decf(unsigned u) {
    return (u & 0x80000000u) ? __uint_as_float(u & 0x7fffffffu) : __uint_as_float(~u);
}

__device__ __forceinline__ uint32_t smem_u32(const void* p) {
    uint32_t a;
    asm("{ .reg .u64 t; cvta.to.shared.u64 t, %1; cvt.u32.u64 %0, t; }" : "=r"(a) : "l"(p));
    return a;
}
__device__ __forceinline__ uint32_t swz(uint32_t off) { return off ^ ((off >> 3) & 0x70); }

__device__ __forceinline__ void cp16(uint32_t dst, const void* src) {
    asm volatile("cp.async.cg.shared.global [%0], [%1], 16;" :: "r"(dst), "l"(src) : "memory");
}
#define CP_COMMIT()  asm volatile("cp.async.commit_group;" ::: "memory")
#define CP_WAIT(n)   asm volatile("cp.async.wait_group %0;" :: "n"(n) : "memory")

#define LDSM_X4(R0, R1, R2, R3, ADDR) \
    asm volatile("ldmatrix.sync.aligned.m8n8.x4.shared.b16 {%0,%1,%2,%3}, [%4];" \
        : "=r"(R0), "=r"(R1), "=r"(R2), "=r"(R3) : "r"(ADDR))

#define MMA_F16(d, a, b) \
    asm volatile("mma.sync.aligned.m16n8k16.row.col.f32.f16.f16.f32 " \
        "{%0,%1,%2,%3}, {%4,%5,%6,%7}, {%8,%9}, {%0,%1,%2,%3};" \
        : "+f"((d)[0]), "+f"((d)[1]), "+f"((d)[2]), "+f"((d)[3]) \
        : "r"((a)[0]), "r"((a)[1]), "r"((a)[2]), "r"((a)[3]), \
          "r"((b)[0]), "r"((b)[1]))

struct alignas(16) H8 { __half2 h[4]; };

// ---------------------------------------------------------------------------
// Kernel 1: L2-normalize -> fp16 (two rows per warp, STG.128), init g_rmax
// and the done-counter (graph-replay safe reset).
// ---------------------------------------------------------------------------
__global__ void k_normalize(const float* __restrict__ x) {
    int gtid = blockIdx.x * blockDim.x + threadIdx.x;
    int p = gtid >> 5;
    int lane = threadIdx.x & 31;
    if (gtid == 0) g_done = 0;
    if (p < N / 2) {
        const int r0 = 2 * p, r1 = 2 * p + 1;
        const float4* xa = reinterpret_cast<const float4*>(x + (size_t)r0 * D);
        const float4* xb = reinterpret_cast<const float4*>(x + (size_t)r1 * D);
        float4 a0 = xa[2 * lane], a1 = xa[2 * lane + 1];
        float4 b0 = xb[2 * lane], b1 = xb[2 * lane + 1];
        float s0 = a0.x * a0.x + a0.y * a0.y + a0.z * a0.z + a0.w * a0.w
                 + a1.x * a1.x + a1.y * a1.y + a1.z * a1.z + a1.w * a1.w;
        float s1 = b0.x * b0.x + b0.y * b0.y + b0.z * b0.z + b0.w * b0.w
                 + b1.x * b1.x + b1.y * b1.y + b1.z * b1.z + b1.w * b1.w;
        #pragma unroll
        for (int o = 16; o; o >>= 1) {
            s0 += __shfl_xor_sync(0xFFFFFFFFu, s0, o);
            s1 += __shfl_xor_sync(0xFFFFFFFFu, s1, o);
        }
        float i0 = rsqrtf(s0), i1 = rsqrtf(s1);
        H8 va, vb;
        va.h[0] = __floats2half2_rn(a0.x * i0, a0.y * i0);
        va.h[1] = __floats2half2_rn(a0.z * i0, a0.w * i0);
        va.h[2] = __floats2half2_rn(a1.x * i0, a1.y * i0);
        va.h[3] = __floats2half2_rn(a1.z * i0, a1.w * i0);
        vb.h[0] = __floats2half2_rn(b0.x * i1, b0.y * i1);
        vb.h[1] = __floats2half2_rn(b0.z * i1, b0.w * i1);
        vb.h[2] = __floats2half2_rn(b1.x * i1, b1.y * i1);
        vb.h[3] = __floats2half2_rn(b1.z * i1, b1.w * i1);
        reinterpret_cast<H8*>(g_xn + (size_t)r0 * D)[lane] = va;
        reinterpret_cast<H8*>(g_xn + (size_t)r1 * D)[lane] = vb;
    }
    if (gtid < N) g_rmax[gtid] = encf(-2.0f);
}

// ---------------------------------------------------------------------------
// Kernel 2: 128x128 tile of S via mma.sync fp16, fused row/col max;
// last CTA (atomic ticket) computes the final loss.
// ---------------------------------------------------------------------------
__global__ __launch_bounds__(NTH, 2)
void k_gemm_max(float* __restrict__ out) {
    const int t = blockIdx.x;
    int mb = (int)((2.0f * NBK + 1.0f - sqrtf((2.0f * NBK + 1.0f) * (2.0f * NBK + 1.0f)
                                              - 8.0f * (float)t)) * 0.5f);
    while (mb * NBK - (mb * (mb - 1)) / 2 > t) mb--;
    while ((mb + 1) * NBK - ((mb + 1) * mb) / 2 <= t) mb++;
    const int nb = mb + (t - (mb * NBK - (mb * (mb - 1)) / 2));

    extern __shared__ char dsm[];
    __shared__ unsigned redrow[BM], redcol[BN];
    __shared__ float sred[NTH];
    __shared__ unsigned s_ticket;

    const int tid  = threadIdx.x;
    const int wid  = tid >> 5;
    const int lane = tid & 31;
    const int wm   = (wid & 3) * 32;   // warp M offset
    const int wn   = (wid >> 2) * 64;  // warp N offset
    const int mrow0 = mb * BM;
    const int nrow0 = nb * BN;

    if (tid < 128) { redrow[tid] = encf(-2.0f); redcol[tid] = encf(-2.0f); }

    const uint32_t sb = smem_u32(dsm);

    auto stage_load = [&](int buf, int k0) {
        uint32_t As = sb + buf * STAGE_BYTES;
        uint32_t Bs = As + 16384;
        #pragma unroll
        for (int i = 0; i < 4; i++) {
            int idx = tid + i * NTH;            // 0..1023
            int r = idx >> 3, c8 = idx & 7;
            cp16(As + swz(r * 128 + c8 * 16),
                 g_xn + (size_t)(mrow0 + r) * D + k0 + c8 * 8);
            cp16(Bs + swz(r * 128 + c8 * 16),
                 g_xn + (size_t)(nrow0 + r) * D + k0 + c8 * 8);
        }
    };

    float acc[2][8][4];
    #pragma unroll
    for (int mt = 0; mt < 2; mt++)
        #pragma unroll
        for (int nt = 0; nt < 8; nt++)
            #pragma unroll
            for (int q = 0; q < 4; q++) acc[mt][nt][q] = 0.0f;

    const int mat  = lane >> 3;
    const int rofs = (mat & 1) * 8 + (lane & 7);
    const int ksel = mat >> 1;
    const int l7   = lane & 7;

    stage_load(0, 0);
    CP_COMMIT();

    #pragma unroll 1
    for (int s = 0; s < NSTAGE; s++) {
        if (s + 1 < NSTAGE) { stage_load((s + 1) & 1, (s + 1) * BK); CP_COMMIT(); CP_WAIT(1); }
        else                { CP_WAIT(0); }
        __syncthreads();

        const uint32_t As = sb + (s & 1) * STAGE_BYTES;
        const uint32_t Bs = As + 16384;

        #pragma unroll
        for (int kk = 0; kk < 4; kk++) {
            uint32_t a[2][4];
            #pragma unroll
            for (int mt = 0; mt < 2; mt++) {
                int row = wm + mt * 16 + rofs;
                uint32_t ad = As + row * 128 + (((kk * 2 + ksel) ^ l7) << 4);
                LDSM_X4(a[mt][0], a[mt][1], a[mt][2], a[mt][3], ad);
            }
            uint32_t b[8][2];
            #pragma unroll
            for (int np = 0; np < 4; np++) {
                int row = wn + np * 16 + rofs;
                uint32_t bd = Bs + row * 128 + (((kk * 2 + ksel) ^ l7) << 4);
                uint32_t q0, q1, q2, q3;
                LDSM_X4(q0, q1, q2, q3, bd);
                b[2 * np][0] = q0;     b[2 * np][1] = q2;
                b[2 * np + 1][0] = q1; b[2 * np + 1][1] = q3;
            }
            #pragma unroll
            for (int mt = 0; mt < 2; mt++)
                #pragma unroll
                for (int nt = 0; nt < 8; nt++)
                    MMA_F16(acc[mt][nt], a[mt], b[nt]);
        }
        __syncthreads();
    }

    // ---- fused epilogue ----
    const int r0 = lane >> 2;
    const int c0 = (lane & 3) * 2;

    #pragma unroll
    for (int mt = 0; mt < 2; mt++)
        #pragma unroll
        for (int rh = 0; rh < 2; rh++) {
            const int lrow = wm + mt * 16 + rh * 8 + r0;
            const int gi = mrow0 + lrow;
            float rm = -2.0f;
            #pragma unroll
            for (int nt = 0; nt < 8; nt++)
                #pragma unroll
                for (int bq = 0; bq < 2; bq++) {
                    int gj = nrow0 + wn + nt * 8 + c0 + bq;
                    float v = acc[mt][nt][rh * 2 + bq];
                    rm = fmaxf(rm, (gi == gj) ? -2.0f : v);
                }
            rm = fmaxf(rm, __shfl_xor_sync(0xFFFFFFFFu, rm, 1));
            rm = fmaxf(rm, __shfl_xor_sync(0xFFFFFFFFu, rm, 2));
            if ((lane & 3) == 0) atomicMax(&redrow[lrow], encf(rm));
        }

    #pragma unroll
    for (int nt = 0; nt < 8; nt++)
        #pragma unroll
        for (int bq = 0; bq < 2; bq++) {
            const int lcol = wn + nt * 8 + c0 + bq;
            const int gj = nrow0 + lcol;
            float cm = -2.0f;
            #pragma unroll
            for (int mt = 0; mt < 2; mt++)
                #pragma unroll
                for (int rh = 0; rh < 2; rh++) {
                    int gi = mrow0 + wm + mt * 16 + rh * 8 + r0;
                    float v = acc[mt][nt][rh * 2 + bq];
                    cm = fmaxf(cm, (gi == gj) ? -2.0f : v);
                }
            cm = fmaxf(cm, __shfl_xor_sync(0xFFFFFFFFu, cm, 4));
            cm = fmaxf(cm, __shfl_xor_sync(0xFFFFFFFFu, cm, 8));
            cm = fmaxf(cm, __shfl_xor_sync(0xFFFFFFFFu, cm, 16));
            if (lane < 4) atomicMax(&redcol[lcol], encf(cm));
        }

    __syncthreads();
    if (tid < 128) {
        atomicMax(&g_rmax[mrow0 + tid], redrow[tid]);
        atomicMax(&g_rmax[nrow0 + tid], redcol[tid]);
    }

    // ---- last-CTA finalize ----
    __threadfence();
    __syncthreads();
    if (tid == 0) s_ticket = atomicAdd(&g_done, 1u);
    __syncthreads();
    if (s_ticket == NTILES - 1) {
        float s = 0.0f;
        #pragma unroll 4
        for (int i = tid; i < N; i += NTH) {
            float smax = decf(g_rmax[i]);
            float d2 = fmaxf(2.0f - 2.0f * smax, 1e-30f);
            s += fmaxf(0.1f, rsqrtf(d2));
        }
        sred[tid] = s;
        __syncthreads();
        #pragma unroll
        for (int o = NTH / 2; o; o >>= 1) {
            if (tid < o) sred[tid] += sred[tid + o];
            __syncthreads();
        }
        if (tid == 0) out[0] = sred[0] / (float)N;
    }
}

extern "C" void kernel_launch(void* const* d_in, const int* in_sizes, int n_in,
                              void* d_out, int out_size) {
    const float* x = (const float*)d_in[0];
    float* out = (float*)d_out;

    cudaFuncSetAttribute(k_gemm_max, cudaFuncAttributeMaxDynamicSharedMemorySize, SMEM_DYN);

    k_normalize<<<(N / 2 * 32) / 256, 256>>>(x);
    k_gemm_max<<<NTILES, NTH, SMEM_DYN>>>(out);
}